// round 6
// baseline (speedup 1.0000x reference)
#include <cuda_runtime.h>
#include <cuda_bf16.h>
#include <cuda_fp16.h>

#define NN   50000
#define NE   800000
#define FIN  128
#define FOUT 64
#define SLOPE 0.2f
#define SCAN_NB ((NN + 255) / 256)   // 196

// ---------------- scratch (__device__ globals; no allocations allowed) -----
__device__ __align__(256) uint2 g_h16[(size_t)NN * 16];  // h as fp16: 64 halfs = 16 uint2 = 128B/row
__device__ float    g_asrc[NN];            // h . att_src   (fp32)
__device__ float    g_adst[NN];            // h . att_dst   (fp32)
__device__ int      g_cnt[NN];             // in-degree (zeroed by k_agg each run)
__device__ int      g_start[NN];           // CSR offsets
__device__ int      g_cursor[NN];          // scatter cursors
__device__ int      g_src[NE];             // CSR: src per edge (dst-sorted)
__device__ unsigned g_state[SCAN_NB];      // lookback: state<<30 | partial

__device__ __forceinline__ float leaky(float v) { return v > 0.f ? v : SLOPE * v; }

// packed f32x2 helpers (FFMA2 is PTX-only; ptxas never auto-fuses)
__device__ __forceinline__ long long pk2(float lo, float hi) {
    long long r;
    asm("mov.b64 %0, {%1,%2};" : "=l"(r) : "f"(lo), "f"(hi));
    return r;
}
__device__ __forceinline__ void unpk2(long long v, float& lo, float& hi) {
    asm("mov.b64 {%0,%1}, %2;" : "=f"(lo), "=f"(hi) : "l"(v));
}
__device__ __forceinline__ long long ffma2(long long a, long long b, long long c) {
    long long d;
    asm("fma.rn.f32x2 %0, %1, %2, %3;" : "=l"(d) : "l"(a), "l"(b), "l"(c));
    return d;
}

// ---------------------------------------------------------------------------
// K1: dst histogram; block 0 also resets the lookback state for k_scan.
//     (g_cnt arrives zeroed: static init on run 1, zeroed by k_agg after.)
// ---------------------------------------------------------------------------
__global__ __launch_bounds__(256) void k_count(const int* __restrict__ ei)
{
    if (blockIdx.x == 0 && threadIdx.x < SCAN_NB) g_state[threadIdx.x] = 0;
    int i = blockIdx.x * blockDim.x + threadIdx.x;
    if (i < NE) atomicAdd(&g_cnt[ei[NE + i]], 1);
}

// ---------------------------------------------------------------------------
// K2: h = x @ W with packed f32x2 FMAs; 4 rows/warp.
//     Epilogue: fp16 h row, fp32 a_src/a_dst.
// ---------------------------------------------------------------------------
#define GEMM_ROWS 16          // rows per block (4 warps x 4 rows)
__global__ __launch_bounds__(128) void k_gemm(
    const float* __restrict__ x, const float* __restrict__ W,
    const float* __restrict__ att_src, const float* __restrict__ att_dst)
{
    __shared__ long long Wsh[FIN * 32];        // 32 KB
    __shared__ long long Xd[GEMM_ROWS * FIN];  // 16 KB: x duplicated (v,v)

    int tid = threadIdx.x;
    int row0 = blockIdx.x * GEMM_ROWS;

    const float2* W2 = (const float2*)W;
    for (int idx = tid; idx < FIN * 32; idx += 128) {
        float2 wv = W2[idx];
        Wsh[idx] = pk2(wv.x, wv.y);
    }
    for (int idx = tid; idx < GEMM_ROWS * 32; idx += 128) {
        int r = idx >> 5, c = idx & 31;
        int row = row0 + r;
        float4 v = (row < NN) ? ((const float4*)(x + (size_t)row * FIN))[c]
                              : make_float4(0.f, 0.f, 0.f, 0.f);
        long long* dst = &Xd[r * FIN + c * 4];
        dst[0] = pk2(v.x, v.x); dst[1] = pk2(v.y, v.y);
        dst[2] = pk2(v.z, v.z); dst[3] = pk2(v.w, v.w);
    }
    __syncthreads();

    int lane = tid & 31, w = tid >> 5;
    float2 as2 = ((const float2*)att_src)[lane];
    float2 ad2 = ((const float2*)att_dst)[lane];

    long long acc[4] = {0, 0, 0, 0};
    #pragma unroll 4
    for (int k = 0; k < FIN; k += 2) {
        long long w0 = Wsh[k * 32 + lane];
        long long w1 = Wsh[(k + 1) * 32 + lane];
        #pragma unroll
        for (int r = 0; r < 4; r++) {
            longlong2 xx = *(const longlong2*)&Xd[(w * 4 + r) * FIN + k];
            acc[r] = ffma2(xx.x, w0, acc[r]);
            acc[r] = ffma2(xx.y, w1, acc[r]);
        }
    }

    #pragma unroll
    for (int r = 0; r < 4; r++) {
        int row = row0 + w * 4 + r;
        if (row >= NN) continue;
        float a0, a1; unpk2(acc[r], a0, a1);
        // fp16 store: lane covers features (2*lane, 2*lane+1) -> one half2 (4B)
        ((__half2*)&g_h16[(size_t)row * 16])[lane] = __floats2half2_rn(a0, a1);
        float ps = a0 * as2.x + a1 * as2.y;
        float pd = a0 * ad2.x + a1 * ad2.y;
        #pragma unroll
        for (int off = 16; off; off >>= 1) {
            ps += __shfl_xor_sync(0xffffffffu, ps, off);
            pd += __shfl_xor_sync(0xffffffffu, pd, off);
        }
        if (lane == 0) { g_asrc[row] = ps; g_adst[row] = pd; }
    }
}

// ---------------------------------------------------------------------------
// K3: single-pass exclusive scan (decoupled lookback), 196 blocks.
//     state word: bits[31:30] 0=invalid 1=aggregate 2=inclusive; bits[29:0] value
// ---------------------------------------------------------------------------
__global__ __launch_bounds__(256) void k_scan()
{
    __shared__ int sm[256];
    __shared__ int s_prefix;
    int t = threadIdx.x, b = blockIdx.x;
    int idx = b * 256 + t;
    int v = (idx < NN) ? g_cnt[idx] : 0;
    sm[t] = v;
    __syncthreads();
    #pragma unroll
    for (int off = 1; off < 256; off <<= 1) {
        int u = (t >= off) ? sm[t - off] : 0;
        __syncthreads();
        sm[t] += u;
        __syncthreads();
    }
    int incl = sm[t];
    int agg  = sm[255];

    if (t == 0) {
        if (b == 0) {
            atomicExch(&g_state[0], (2u << 30) | (unsigned)agg);
            s_prefix = 0;
        } else {
            atomicExch(&g_state[b], (1u << 30) | (unsigned)agg);
            int pre = 0, j = b - 1;
            while (true) {
                unsigned s = atomicAdd(&g_state[j], 0u);
                unsigned st = s >> 30;
                if (st == 0u) continue;                 // not ready, spin
                pre += (int)(s & 0x3fffffffu);
                if (st == 2u) break;                    // found inclusive prefix
                j--;
            }
            s_prefix = pre;
            atomicExch(&g_state[b], (2u << 30) | (unsigned)(pre + agg));
        }
    }
    __syncthreads();
    if (idx < NN) {
        int excl = s_prefix + incl - v;
        g_start[idx]  = excl;
        g_cursor[idx] = excl;
    }
}

// ---------------------------------------------------------------------------
// K4: scatter edges into dst-sorted CSR
// ---------------------------------------------------------------------------
__global__ __launch_bounds__(256) void k_scatter(const int* __restrict__ ei)
{
    int i = blockIdx.x * blockDim.x + threadIdx.x;
    if (i >= NE) return;
    int d = ei[NE + i];
    int pos = atomicAdd(&g_cursor[d], 1);
    g_src[pos] = ei[i];
}

// ---------------------------------------------------------------------------
// K5: one warp per dst node; two half-warp edge streams with online-softmax;
//     fp16 h gathered as one 128B line per edge (16 lanes x uint2).
//     Self loop folded into half 0's init. Zeroes g_cnt for next run.
// ---------------------------------------------------------------------------
__global__ __launch_bounds__(256) void k_agg(float* __restrict__ out,
                                             const float* __restrict__ bias)
{
    int gw = (blockIdx.x * 256 + threadIdx.x) >> 5;
    int lane = threadIdx.x & 31;
    if (gw >= NN) return;
    int d = gw;
    int eh = lane >> 4, f = lane & 15;          // half-warp id, feature group

    int beg = g_start[d];
    int cnt = g_cnt[d];
    float adst_d = g_adst[d];
    float sl = leaky(g_asrc[d] + adst_d);       // self-loop logit

    float m, ssum;
    float4 acc;                                  // 4 features per lane
    if (eh == 0) {
        m = sl; ssum = 1.f;
        uint2 hv = g_h16[(size_t)d * 16 + f];
        float2 lo = __half22float2(*(__half2*)&hv.x);
        float2 hi = __half22float2(*(__half2*)&hv.y);
        acc = make_float4(lo.x, lo.y, hi.x, hi.y);
    } else {
        m = -1e30f; ssum = 0.f;
        acc = make_float4(0.f, 0.f, 0.f, 0.f);
    }

    for (int base = 0; base < cnt; base += 32) {
        int n = cnt - base; if (n > 32) n = 32;
        int s = 0; float e = -1e30f;
        if (lane < n) {
            s = g_src[beg + base + lane];
            e = leaky(__ldg(&g_asrc[s]) + adst_d);
        }
        for (int j0 = 0; j0 < n; j0 += 8) {      // 8 edges: 4 per half-warp
            uint2 hb[4]; float ee[4];
            #pragma unroll
            for (int u = 0; u < 4; u++) {
                int j = j0 + 2 * u + eh;
                int ss = __shfl_sync(0xffffffffu, s, j);
                ee[u]  = __shfl_sync(0xffffffffu, e, j);
                hb[u]  = g_h16[(size_t)ss * 16 + f];   // 128B line per edge
            }
            #pragma unroll
            for (int u = 0; u < 4; u++) {
                float ev = ee[u];                // uniform within half-warp
                if (ev > m) {
                    float c = __expf(m - ev);
                    ssum *= c;
                    acc.x *= c; acc.y *= c; acc.z *= c; acc.w *= c;
                    m = ev;
                }
                float p = __expf(ev - m);        // 0 for padded edges
                ssum += p;
                float2 lo = __half22float2(*(__half2*)&hb[u].x);
                float2 hi = __half22float2(*(__half2*)&hb[u].y);
                acc.x += p * lo.x; acc.y += p * lo.y;
                acc.z += p * hi.x; acc.w += p * hi.y;
            }
        }
    }

    // merge the two half-warp softmax states
    float mo = __shfl_xor_sync(0xffffffffu, m, 16);
    float so = __shfl_xor_sync(0xffffffffu, ssum, 16);
    float4 ao;
    ao.x = __shfl_xor_sync(0xffffffffu, acc.x, 16);
    ao.y = __shfl_xor_sync(0xffffffffu, acc.y, 16);
    ao.z = __shfl_xor_sync(0xffffffffu, acc.z, 16);
    ao.w = __shfl_xor_sync(0xffffffffu, acc.w, 16);
    float M  = fmaxf(m, mo);
    float c0 = __expf(m - M), c1 = __expf(mo - M);
    float inv = 1.f / (ssum * c0 + so * c1);

    if (eh == 0) {
        float4 bv = ((const float4*)bias)[f];
        float4 r;
        r.x = (acc.x * c0 + ao.x * c1) * inv + bv.x;
        r.y = (acc.y * c0 + ao.y * c1) * inv + bv.y;
        r.z = (acc.z * c0 + ao.z * c1) * inv + bv.z;
        r.w = (acc.w * c0 + ao.w * c1) * inv + bv.w;
        ((float4*)(out + (size_t)d * FOUT))[f] = r;
    }
    if (lane == 0) g_cnt[d] = 0;                 // ready for next run
}

// ---------------------------------------------------------------------------
extern "C" void kernel_launch(void* const* d_in, const int* in_sizes, int n_in,
                              void* d_out, int out_size)
{
    const float* x    = (const float*)d_in[0];
    const int*   ei   = (const int*)  d_in[1];   // [2, NE]: row0=src, row1=dst
    const float* W    = (const float*)d_in[2];
    const float* asrc = (const float*)d_in[3];
    const float* adst = (const float*)d_in[4];
    const float* bias = (const float*)d_in[5];
    float* out = (float*)d_out;

    static cudaStream_t s1 = nullptr;
    static cudaEvent_t ev_fork = nullptr, ev_join = nullptr;
    if (s1 == nullptr) {
        cudaStreamCreateWithFlags(&s1, cudaStreamNonBlocking);
        cudaEventCreateWithFlags(&ev_fork, cudaEventDisableTiming);
        cudaEventCreateWithFlags(&ev_join, cudaEventDisableTiming);
    }

    // fork: GEMM (x,W only) on s1 concurrent with CSR build (ei only)
    cudaEventRecord(ev_fork, 0);
    cudaStreamWaitEvent(s1, ev_fork, 0);
    k_gemm<<<(NN + GEMM_ROWS - 1) / GEMM_ROWS, 128, 0, s1>>>(x, W, asrc, adst);
    cudaEventRecord(ev_join, s1);

    k_count  <<<(NE + 255) / 256, 256>>>(ei);
    k_scan   <<<SCAN_NB, 256>>>();
    k_scatter<<<(NE + 255) / 256, 256>>>(ei);

    cudaStreamWaitEvent(0, ev_join, 0);          // join before aggregation
    k_agg<<<(NN * 32 + 255) / 256, 256>>>(out, bias);
}

// round 9
// speedup vs baseline: 1.1077x; 1.1077x over previous
#include <cuda_runtime.h>
#include <cuda_bf16.h>
#include <cuda_fp16.h>

#define NN   50000
#define NE   800000
#define FIN  128
#define FOUT 64
#define SLOPE 0.2f
#define SCAN_NB ((NN + 255) / 256)   // 196

// ---------------- scratch (__device__ globals; no allocations allowed) -----
__device__ __align__(256) uint4 g_h16[(size_t)NN * 8];  // h fp16: 64 halfs = 128B/row
__device__ float          g_asrc[NN];       // h . att_src (fp32)
__device__ float          g_adst[NN];       // h . att_dst (fp32)
__device__ int            g_cnt[NN];        // in-degree (zeroed by k_agg each run)
__device__ int            g_start[NN];      // CSR offsets
__device__ unsigned short g_rank[NE];       // edge rank within its dst segment
__device__ int            g_src[NE];        // CSR: src per edge (dst-sorted)
__device__ unsigned       g_state[SCAN_NB]; // lookback: state<<30 | value

__device__ __forceinline__ float leaky(float v) { return v > 0.f ? v : SLOPE * v; }

// packed f32x2 helpers (FFMA2 is PTX-only; ptxas never auto-fuses)
__device__ __forceinline__ long long pk2(float lo, float hi) {
    long long r;
    asm("mov.b64 %0, {%1,%2};" : "=l"(r) : "f"(lo), "f"(hi));
    return r;
}
__device__ __forceinline__ void unpk2(long long v, float& lo, float& hi) {
    asm("mov.b64 {%0,%1}, %2;" : "=f"(lo), "=f"(hi) : "l"(v));
}
__device__ __forceinline__ long long ffma2(long long a, long long b, long long c) {
    long long d;
    asm("fma.rn.f32x2 %0, %1, %2, %3;" : "=l"(d) : "l"(a), "l"(b), "l"(c));
    return d;
}

__device__ __forceinline__ void cvt8(float* f, uint4 hv) {
    float2 a = __half22float2(*(__half2*)&hv.x);
    float2 b = __half22float2(*(__half2*)&hv.y);
    float2 c = __half22float2(*(__half2*)&hv.z);
    float2 d = __half22float2(*(__half2*)&hv.w);
    f[0] = a.x; f[1] = a.y; f[2] = b.x; f[3] = b.y;
    f[4] = c.x; f[5] = c.y; f[6] = d.x; f[7] = d.y;
}

// ---------------------------------------------------------------------------
// K1: dst histogram; keeps the atomic's return as the edge's rank.
//     Block 0 also resets the lookback state. g_cnt arrives zeroed.
// ---------------------------------------------------------------------------
__global__ __launch_bounds__(256) void k_count(const int* __restrict__ ei)
{
    if (blockIdx.x == 0 && threadIdx.x < SCAN_NB) g_state[threadIdx.x] = 0;
    int i = blockIdx.x * blockDim.x + threadIdx.x;
    if (i < NE) {
        int d = ei[NE + i];
        g_rank[i] = (unsigned short)atomicAdd(&g_cnt[d], 1);
    }
}

// ---------------------------------------------------------------------------
// K2: h = x @ W with packed f32x2 FMAs; 4 rows/warp.
//     Epilogue: fp16 h row, fp32 a_src/a_dst.
// ---------------------------------------------------------------------------
#define GEMM_ROWS 16          // rows per block (4 warps x 4 rows)
__global__ __launch_bounds__(128) void k_gemm(
    const float* __restrict__ x, const float* __restrict__ W,
    const float* __restrict__ att_src, const float* __restrict__ att_dst)
{
    __shared__ long long Wsh[FIN * 32];        // 32 KB
    __shared__ long long Xd[GEMM_ROWS * FIN];  // 16 KB: x duplicated (v,v)

    int tid = threadIdx.x;
    int row0 = blockIdx.x * GEMM_ROWS;

    const float2* W2 = (const float2*)W;
    for (int idx = tid; idx < FIN * 32; idx += 128) {
        float2 wv = W2[idx];
        Wsh[idx] = pk2(wv.x, wv.y);
    }
    for (int idx = tid; idx < GEMM_ROWS * 32; idx += 128) {
        int r = idx >> 5, c = idx & 31;
        int row = row0 + r;
        float4 v = (row < NN) ? ((const float4*)(x + (size_t)row * FIN))[c]
                              : make_float4(0.f, 0.f, 0.f, 0.f);
        long long* dst = &Xd[r * FIN + c * 4];
        dst[0] = pk2(v.x, v.x); dst[1] = pk2(v.y, v.y);
        dst[2] = pk2(v.z, v.z); dst[3] = pk2(v.w, v.w);
    }
    __syncthreads();

    int lane = tid & 31, w = tid >> 5;
    float2 as2 = ((const float2*)att_src)[lane];
    float2 ad2 = ((const float2*)att_dst)[lane];

    long long acc[4] = {0, 0, 0, 0};
    #pragma unroll 4
    for (int k = 0; k < FIN; k += 2) {
        long long w0 = Wsh[k * 32 + lane];
        long long w1 = Wsh[(k + 1) * 32 + lane];
        #pragma unroll
        for (int r = 0; r < 4; r++) {
            longlong2 xx = *(const longlong2*)&Xd[(w * 4 + r) * FIN + k];
            acc[r] = ffma2(xx.x, w0, acc[r]);
            acc[r] = ffma2(xx.y, w1, acc[r]);
        }
    }

    #pragma unroll
    for (int r = 0; r < 4; r++) {
        int row = row0 + w * 4 + r;
        if (row >= NN) continue;
        float a0, a1; unpk2(acc[r], a0, a1);
        ((__half2*)&g_h16[(size_t)row * 8])[lane] = __floats2half2_rn(a0, a1);
        float ps = a0 * as2.x + a1 * as2.y;
        float pd = a0 * ad2.x + a1 * ad2.y;
        #pragma unroll
        for (int off = 16; off; off >>= 1) {
            ps += __shfl_xor_sync(0xffffffffu, ps, off);
            pd += __shfl_xor_sync(0xffffffffu, pd, off);
        }
        if (lane == 0) { g_asrc[row] = ps; g_adst[row] = pd; }
    }
}

// ---------------------------------------------------------------------------
// K3: single-pass exclusive scan (decoupled lookback), 196 blocks
// ---------------------------------------------------------------------------
__global__ __launch_bounds__(256) void k_scan()
{
    __shared__ int sm[256];
    __shared__ int s_prefix;
    int t = threadIdx.x, b = blockIdx.x;
    int idx = b * 256 + t;
    int v = (idx < NN) ? g_cnt[idx] : 0;
    sm[t] = v;
    __syncthreads();
    #pragma unroll
    for (int off = 1; off < 256; off <<= 1) {
        int u = (t >= off) ? sm[t - off] : 0;
        __syncthreads();
        sm[t] += u;
        __syncthreads();
    }
    int incl = sm[t];
    int agg  = sm[255];

    if (t == 0) {
        if (b == 0) {
            atomicExch(&g_state[0], (2u << 30) | (unsigned)agg);
            s_prefix = 0;
        } else {
            atomicExch(&g_state[b], (1u << 30) | (unsigned)agg);
            int pre = 0, j = b - 1;
            while (true) {
                unsigned s = atomicAdd(&g_state[j], 0u);
                unsigned st = s >> 30;
                if (st == 0u) continue;
                pre += (int)(s & 0x3fffffffu);
                if (st == 2u) break;
                j--;
            }
            s_prefix = pre;
            atomicExch(&g_state[b], (2u << 30) | (unsigned)(pre + agg));
        }
    }
    __syncthreads();
    if (idx < NN) g_start[idx] = s_prefix + incl - v;
}

// ---------------------------------------------------------------------------
// K4: scatter WITHOUT atomics: pos = start[dst] + rank
// ---------------------------------------------------------------------------
__global__ __launch_bounds__(256) void k_scatter(const int* __restrict__ ei)
{
    int i = blockIdx.x * blockDim.x + threadIdx.x;
    if (i >= NE) return;
    int d = ei[NE + i];
    g_src[g_start[d] + (int)g_rank[i]] = ei[i];
}

// ---------------------------------------------------------------------------
// K5: 8 lanes per dst node (4 nodes/warp). Softmax normalized by the
//     self-loop logit (shift-invariant => identical math, no online max,
//     1 exp per edge, branch-free). One 128B line per edge gather.
//     Zeroes g_cnt for the next run.
// ---------------------------------------------------------------------------
__global__ __launch_bounds__(256) void k_agg(float* __restrict__ out,
                                             const float* __restrict__ bias)
{
    int gid = (blockIdx.x * 256 + threadIdx.x) >> 3;
    int f = threadIdx.x & 7;
    unsigned segmask = 0xFFu << (threadIdx.x & 24);   // this group's 8 lanes
    bool live = (gid < NN);
    int node = live ? gid : (NN - 1);

    int beg = g_start[node];
    int cnt = g_cnt[node];
    float adst_d = g_adst[node];
    float sl = leaky(g_asrc[node] + adst_d);   // self-loop logit = shift

    float ssum = 1.f;                          // self loop: exp(sl - sl)
    float acc[8];
    cvt8(acc, g_h16[(size_t)node * 8 + f]);    // acc = h[node] (self loop)

    for (int base = 0; base < cnt; base += 8) {
        int nb = cnt - base; if (nb > 8) nb = 8;
        int s = 0; float p = 0.f;
        if (f < nb) {
            s = g_src[beg + base + f];
            p = __expf(leaky(__ldg(&g_asrc[s]) + adst_d) - sl);
        }
        for (int j0 = 0; j0 < nb; j0 += 4) {
            uint4 hb[4]; float pp[4];
            #pragma unroll
            for (int u = 0; u < 4; u++) {
                int ss = __shfl_sync(segmask, s, j0 + u, 8);
                pp[u]  = __shfl_sync(segmask, p, j0 + u, 8);
                hb[u]  = g_h16[(size_t)ss * 8 + f];     // 128B line/edge
            }
            #pragma unroll
            for (int u = 0; u < 4; u++) {
                float pv = pp[u];                        // 0 for padded edges
                ssum += pv;
                float fb[8]; cvt8(fb, hb[u]);
                #pragma unroll
                for (int q = 0; q < 8; q++) acc[q] += pv * fb[q];
            }
        }
        ssum -= 3.f * p;   // lanes replicate ssum; correct: each lane added all pp
        ssum += 3.f * p;   // (no-op kept out: see note) -- removed below
    }

    // NOTE: every lane accumulated the same pp values (broadcast), so ssum is
    // consistent across the group already.
    float inv = 1.f / ssum;
    if (live) {
        float4 b0 = ((const float4*)bias)[f * 2];
        float4 b1 = ((const float4*)bias)[f * 2 + 1];
        float4 r0 = make_float4(acc[0] * inv + b0.x, acc[1] * inv + b0.y,
                                acc[2] * inv + b0.z, acc[3] * inv + b0.w);
        float4 r1 = make_float4(acc[4] * inv + b1.x, acc[5] * inv + b1.y,
                                acc[6] * inv + b1.z, acc[7] * inv + b1.w);
        ((float4*)(out + (size_t)node * FOUT))[f * 2]     = r0;
        ((float4*)(out + (size_t)node * FOUT))[f * 2 + 1] = r1;
        if (f == 0) g_cnt[node] = 0;           // ready for next run
    }
}

// ---------------------------------------------------------------------------
extern "C" void kernel_launch(void* const* d_in, const int* in_sizes, int n_in,
                              void* d_out, int out_size)
{
    const float* x    = (const float*)d_in[0];
    const int*   ei   = (const int*)  d_in[1];   // [2, NE]: row0=src, row1=dst
    const float* W    = (const float*)d_in[2];
    const float* asrc = (const float*)d_in[3];
    const float* adst = (const float*)d_in[4];
    const float* bias = (const float*)d_in[5];
    float* out = (float*)d_out;

    static cudaStream_t s1 = nullptr;
    static cudaEvent_t ev_fork = nullptr, ev_join = nullptr;
    if (s1 == nullptr) {
        cudaStreamCreateWithFlags(&s1, cudaStreamNonBlocking);
        cudaEventCreateWithFlags(&ev_fork, cudaEventDisableTiming);
        cudaEventCreateWithFlags(&ev_join, cudaEventDisableTiming);
    }

    // fork: GEMM (x,W only) on s1 concurrent with CSR build (ei only)
    cudaEventRecord(ev_fork, 0);
    cudaStreamWaitEvent(s1, ev_fork, 0);
    k_gemm<<<(NN + GEMM_ROWS - 1) / GEMM_ROWS, 128, 0, s1>>>(x, W, asrc, adst);
    cudaEventRecord(ev_join, s1);

    k_count  <<<(NE + 255) / 256, 256>>>(ei);
    k_scan   <<<SCAN_NB, 256>>>();
    k_scatter<<<(NE + 255) / 256, 256>>>(ei);

    cudaStreamWaitEvent(0, ev_join, 0);          // join before aggregation
    k_agg<<<(NN * 8 + 255) / 256, 256>>>(out, bias);
}

// round 13
// speedup vs baseline: 1.1258x; 1.0163x over previous
#include <cuda_runtime.h>
#include <cuda_bf16.h>
#include <cuda_fp16.h>

#define NN   50000
#define NE   800000
#define FIN  128
#define FOUT 64
#define SLOPE 0.2f
#define SCAN_NB ((NN + 255) / 256)   // 196

// ---------------- scratch (__device__ globals; no allocations allowed) -----
__device__ __align__(256) uint4 g_h16[(size_t)NN * 8]; // h fp16: 64 halfs=128B/row
__device__ float    g_asrc[NN];          // h . att_src (fp32)
__device__ float4   g_dinfo[NN];         // (a_dst, sl, start_bits, unused)
__device__ int      g_cnt[NN];           // in-degree (zeroed by k_agg each run)
__device__ unsigned g_rkd[NE];           // (dst<<16) | rank
__device__ uint2    g_ep[NE];            // per-edge (src, p) dst-sorted
__device__ unsigned g_state[SCAN_NB];    // lookback: state<<30 | value

__device__ __forceinline__ float leaky(float v) { return v > 0.f ? v : SLOPE * v; }

// packed f32x2 helpers (FFMA2 is PTX-only; ptxas never auto-fuses)
__device__ __forceinline__ long long pk2(float lo, float hi) {
    long long r;
    asm("mov.b64 %0, {%1,%2};" : "=l"(r) : "f"(lo), "f"(hi));
    return r;
}
__device__ __forceinline__ void unpk2(long long v, float& lo, float& hi) {
    asm("mov.b64 {%0,%1}, %2;" : "=f"(lo), "=f"(hi) : "l"(v));
}
__device__ __forceinline__ long long ffma2(long long a, long long b, long long c) {
    long long d;
    asm("fma.rn.f32x2 %0, %1, %2, %3;" : "=l"(d) : "l"(a), "l"(b), "l"(c));
    return d;
}

__device__ __forceinline__ void cvt8(float* f, uint4 hv) {
    float2 a = __half22float2(*(__half2*)&hv.x);
    float2 b = __half22float2(*(__half2*)&hv.y);
    float2 c = __half22float2(*(__half2*)&hv.z);
    float2 d = __half22float2(*(__half2*)&hv.w);
    f[0] = a.x; f[1] = a.y; f[2] = b.x; f[3] = b.y;
    f[4] = c.x; f[5] = c.y; f[6] = d.x; f[7] = d.y;
}

// ---------------------------------------------------------------------------
// K1: dst histogram; stores (dst<<16 | rank) so scatter never re-reads ei row1.
//     Block 0 also resets the lookback state. g_cnt arrives zeroed.
// ---------------------------------------------------------------------------
__global__ __launch_bounds__(256) void k_count(const int* __restrict__ ei)
{
    if (blockIdx.x == 0 && threadIdx.x < SCAN_NB) g_state[threadIdx.x] = 0;
    int i = blockIdx.x * blockDim.x + threadIdx.x;
    if (i < NE) {
        int d = ei[NE + i];
        unsigned r = (unsigned)atomicAdd(&g_cnt[d], 1);
        g_rkd[i] = ((unsigned)d << 16) | (r & 0xffffu);
    }
}

// ---------------------------------------------------------------------------
// K2: h = x @ W (packed f32x2 FMAs, 4 rows/warp).
//     Epilogue: fp16 h row, a_src, and dst-side info (a_dst, sl).
// ---------------------------------------------------------------------------
#define GEMM_ROWS 16          // rows per block (4 warps x 4 rows)
__global__ __launch_bounds__(128) void k_gemm(
    const float* __restrict__ x, const float* __restrict__ W,
    const float* __restrict__ att_src, const float* __restrict__ att_dst)
{
    __shared__ long long Wsh[FIN * 32];        // 32 KB
    __shared__ long long Xd[GEMM_ROWS * FIN];  // 16 KB: x duplicated (v,v)

    int tid = threadIdx.x;
    int row0 = blockIdx.x * GEMM_ROWS;

    const float2* W2 = (const float2*)W;
    for (int idx = tid; idx < FIN * 32; idx += 128) {
        float2 wv = W2[idx];
        Wsh[idx] = pk2(wv.x, wv.y);
    }
    for (int idx = tid; idx < GEMM_ROWS * 32; idx += 128) {
        int r = idx >> 5, c = idx & 31;
        int row = row0 + r;
        float4 v = (row < NN) ? ((const float4*)(x + (size_t)row * FIN))[c]
                              : make_float4(0.f, 0.f, 0.f, 0.f);
        long long* dst = &Xd[r * FIN + c * 4];
        dst[0] = pk2(v.x, v.x); dst[1] = pk2(v.y, v.y);
        dst[2] = pk2(v.z, v.z); dst[3] = pk2(v.w, v.w);
    }
    __syncthreads();

    int lane = tid & 31, w = tid >> 5;
    float2 as2 = ((const float2*)att_src)[lane];
    float2 ad2 = ((const float2*)att_dst)[lane];

    long long acc[4] = {0, 0, 0, 0};
    #pragma unroll 4
    for (int k = 0; k < FIN; k += 2) {
        long long w0 = Wsh[k * 32 + lane];
        long long w1 = Wsh[(k + 1) * 32 + lane];
        #pragma unroll
        for (int r = 0; r < 4; r++) {
            longlong2 xx = *(const longlong2*)&Xd[(w * 4 + r) * FIN + k];
            acc[r] = ffma2(xx.x, w0, acc[r]);
            acc[r] = ffma2(xx.y, w1, acc[r]);
        }
    }

    #pragma unroll
    for (int r = 0; r < 4; r++) {
        int row = row0 + w * 4 + r;
        if (row >= NN) continue;
        float a0, a1; unpk2(acc[r], a0, a1);
        ((__half2*)&g_h16[(size_t)row * 8])[lane] = __floats2half2_rn(a0, a1);
        float ps = a0 * as2.x + a1 * as2.y;
        float pd = a0 * ad2.x + a1 * ad2.y;
        #pragma unroll
        for (int off = 16; off; off >>= 1) {
            ps += __shfl_xor_sync(0xffffffffu, ps, off);
            pd += __shfl_xor_sync(0xffffffffu, pd, off);
        }
        if (lane == 0) {
            g_asrc[row] = ps;
            // (a_dst, sl); .z (start) written later by k_scan
            *(float2*)&g_dinfo[row] = make_float2(pd, leaky(ps + pd));
        }
    }
}

// ---------------------------------------------------------------------------
// K3: single-pass exclusive scan (decoupled lookback), 196 blocks.
//     Writes start into g_dinfo[idx].z (int bits).
// ---------------------------------------------------------------------------
__global__ __launch_bounds__(256) void k_scan()
{
    __shared__ int sm[256];
    __shared__ int s_prefix;
    int t = threadIdx.x, b = blockIdx.x;
    int idx = b * 256 + t;
    int v = (idx < NN) ? g_cnt[idx] : 0;
    sm[t] = v;
    __syncthreads();
    #pragma unroll
    for (int off = 1; off < 256; off <<= 1) {
        int u = (t >= off) ? sm[t - off] : 0;
        __syncthreads();
        sm[t] += u;
        __syncthreads();
    }
    int incl = sm[t];
    int agg  = sm[255];

    if (t == 0) {
        if (b == 0) {
            atomicExch(&g_state[0], (2u << 30) | (unsigned)agg);
            s_prefix = 0;
        } else {
            atomicExch(&g_state[b], (1u << 30) | (unsigned)agg);
            int pre = 0, j = b - 1;
            while (true) {
                unsigned s = atomicAdd(&g_state[j], 0u);
                unsigned st = s >> 30;
                if (st == 0u) continue;
                pre += (int)(s & 0x3fffffffu);
                if (st == 2u) break;
                j--;
            }
            s_prefix = pre;
            atomicExch(&g_state[b], (2u << 30) | (unsigned)(pre + agg));
        }
    }
    __syncthreads();
    if (idx < NN) *(int*)&g_dinfo[idx].z = s_prefix + incl - v;
}

// ---------------------------------------------------------------------------
// K4: scatter resolved edge records: g_ep[start+rank] = (src, p)
//     p = exp(leaky(a_src[s] + a_dst[d]) - sl[d])   (fp32, shift-invariant)
//     Needs GEMM outputs: launched after the join.
// ---------------------------------------------------------------------------
__global__ __launch_bounds__(256) void k_scatter(const int* __restrict__ ei)
{
    int i = blockIdx.x * blockDim.x + threadIdx.x;
    if (i >= NE) return;
    int s = ei[i];
    unsigned rd = g_rkd[i];
    int d = (int)(rd >> 16), rank = (int)(rd & 0xffffu);
    float4 di = g_dinfo[d];                 // (a_dst, sl, start_bits, -)
    float p = __expf(leaky(g_asrc[s] + di.x) - di.y);
    int pos = __float_as_int(di.z) + rank;
    g_ep[pos] = make_uint2((unsigned)s, __float_as_uint(p));
}

// ---------------------------------------------------------------------------
// K5: 8 lanes per dst node (4 nodes/warp). Sequential (src,p) reads with
//     next-batch prefetch; single random access = 128B h-line gather.
//     ssum starts at 1 (self loop), acc starts at h[node]. Zeroes g_cnt.
// ---------------------------------------------------------------------------
__global__ __launch_bounds__(256) void k_agg(float* __restrict__ out,
                                             const float* __restrict__ bias)
{
    int gid = (blockIdx.x * 256 + threadIdx.x) >> 3;
    int f = threadIdx.x & 7;
    unsigned segmask = 0xFFu << (threadIdx.x & 24);   // this group's 8 lanes
    bool live = (gid < NN);
    int node = live ? gid : (NN - 1);

    float4 di = g_dinfo[node];
    int beg = __float_as_int(di.z);
    int cnt = g_cnt[node];

    float ssum = 1.f;                          // self loop: exp(sl-sl)
    float acc[8];
    cvt8(acc, g_h16[(size_t)node * 8 + f]);    // self-loop contribution

    // prefetch batch 0
    uint2 ev = make_uint2(0u, 0u);
    if (cnt > 0 && f < cnt) ev = g_ep[beg + f];

    for (int base = 0; base < cnt; base += 8) {
        int nb = cnt - base; if (nb > 8) nb = 8;
        unsigned s = ev.x;
        float p = __uint_as_float(ev.y);
        if (f >= nb) { s = 0u; p = 0.f; }

        // prefetch next batch while we chew on this one
        ev = make_uint2(0u, 0u);
        int nxt = base + 8;
        if (nxt < cnt && f < cnt - nxt) ev = g_ep[beg + nxt + f];

        for (int j0 = 0; j0 < nb; j0 += 4) {
            uint4 hb[4]; float pp[4];
            #pragma unroll
            for (int u = 0; u < 4; u++) {
                unsigned ss = __shfl_sync(segmask, s, j0 + u, 8);
                pp[u]       = __shfl_sync(segmask, p, j0 + u, 8);
                hb[u]       = g_h16[(size_t)ss * 8 + f];   // 128B line/edge
            }
            #pragma unroll
            for (int u = 0; u < 4; u++) {
                float pv = pp[u];                 // 0 for padded edges
                ssum += pv;
                float fb[8]; cvt8(fb, hb[u]);
                #pragma unroll
                for (int q = 0; q < 8; q++) acc[q] += pv * fb[q];
            }
        }
    }

    float inv = 1.f / ssum;
    if (live) {
        float4 b0 = ((const float4*)bias)[f * 2];
        float4 b1 = ((const float4*)bias)[f * 2 + 1];
        float4 r0 = make_float4(acc[0] * inv + b0.x, acc[1] * inv + b0.y,
                                acc[2] * inv + b0.z, acc[3] * inv + b0.w);
        float4 r1 = make_float4(acc[4] * inv + b1.x, acc[5] * inv + b1.y,
                                acc[6] * inv + b1.z, acc[7] * inv + b1.w);
        ((float4*)(out + (size_t)node * FOUT))[f * 2]     = r0;
        ((float4*)(out + (size_t)node * FOUT))[f * 2 + 1] = r1;
        if (f == 0) g_cnt[node] = 0;              // ready for next run
    }
}

// ---------------------------------------------------------------------------
extern "C" void kernel_launch(void* const* d_in, const int* in_sizes, int n_in,
                              void* d_out, int out_size)
{
    const float* x    = (const float*)d_in[0];
    const int*   ei   = (const int*)  d_in[1];   // [2, NE]: row0=src, row1=dst
    const float* W    = (const float*)d_in[2];
    const float* asrc = (const float*)d_in[3];
    const float* adst = (const float*)d_in[4];
    const float* bias = (const float*)d_in[5];
    float* out = (float*)d_out;

    static cudaStream_t s1 = nullptr;
    static cudaEvent_t ev_fork = nullptr, ev_join = nullptr;
    if (s1 == nullptr) {
        cudaStreamCreateWithFlags(&s1, cudaStreamNonBlocking);
        cudaEventCreateWithFlags(&ev_fork, cudaEventDisableTiming);
        cudaEventCreateWithFlags(&ev_join, cudaEventDisableTiming);
    }

    // fork: GEMM (x,W only) on s1, concurrent with count+scan (ei only)
    cudaEventRecord(ev_fork, 0);
    cudaStreamWaitEvent(s1, ev_fork, 0);
    k_gemm<<<(NN + GEMM_ROWS - 1) / GEMM_ROWS, 128, 0, s1>>>(x, W, asrc, adst);
    cudaEventRecord(ev_join, s1);

    k_count<<<(NE + 255) / 256, 256>>>(ei);
    k_scan <<<SCAN_NB, 256>>>();

    cudaStreamWaitEvent(0, ev_join, 0);          // scatter needs GEMM outputs
    k_scatter<<<(NE + 255) / 256, 256>>>(ei);
    k_agg<<<(NN * 8 + 255) / 256, 256>>>(out, bias);
}